// round 1
// baseline (speedup 1.0000x reference)
#include <cuda_runtime.h>

#define B_      2
#define L_      4096
#define HIDDEN  512
#define HEADS   8
#define HD      64
#define PREFIX  1
#define M_ROWS  (B_ * L_)        // 8192

// Scratch (allocation-free rule: __device__ globals)
__device__ float g_q[B_ * HEADS * L_ * HD];
__device__ float g_k[B_ * HEADS * L_ * HD];
__device__ float g_v[B_ * HEADS * L_ * HD];
__device__ float g_ctx[B_ * L_ * HIDDEN];

// ============================================================
// SGEMM 128x128x8, 256 threads, 8x8 per thread (split-half frags)
// EPI=0: C = A@B + bias scattered into g_q/g_k/g_v ([B,H,L,hd])
// EPI=1: C = g_ctx@B + bias stored plain row-major into C
// ============================================================
template <int EPI>
__global__ __launch_bounds__(256) void sgemm_kernel(
    const float* __restrict__ A_in, const float* __restrict__ B_in,
    const float* __restrict__ bias, float* __restrict__ C,
    int M, int N, int K)
{
    __shared__ float As[8][128];
    __shared__ float Bs[8][128];

    const float* A = (EPI == 1) ? (const float*)g_ctx : A_in;

    int tid = threadIdx.x;
    int tx = tid & 15, ty = tid >> 4;
    int bm = blockIdx.y, bn = blockIdx.x;

    float acc[8][8];
#pragma unroll
    for (int i = 0; i < 8; i++)
#pragma unroll
        for (int j = 0; j < 8; j++) acc[i][j] = 0.f;

    int arow = tid >> 1;
    int acol = (tid & 1) << 2;
    int brow = tid >> 5;
    int bcol = (tid & 31) << 2;

    const float* Ap = A + (size_t)(bm * 128 + arow) * K + acol;
    const float* Bp = B_in + (size_t)brow * N + bn * 128 + bcol;

    for (int kt = 0; kt < K; kt += 8) {
        float4 a4 = *(const float4*)(Ap + kt);
        float4 b4 = *(const float4*)(Bp + (size_t)kt * N);
        As[acol + 0][arow] = a4.x;
        As[acol + 1][arow] = a4.y;
        As[acol + 2][arow] = a4.z;
        As[acol + 3][arow] = a4.w;
        *(float4*)&Bs[brow][bcol] = b4;
        __syncthreads();

#pragma unroll
        for (int k = 0; k < 8; k++) {
            float af[8], bf[8];
            *(float4*)&af[0] = *(const float4*)&As[k][ty << 2];
            *(float4*)&af[4] = *(const float4*)&As[k][64 + (ty << 2)];
            *(float4*)&bf[0] = *(const float4*)&Bs[k][tx << 2];
            *(float4*)&bf[4] = *(const float4*)&Bs[k][64 + (tx << 2)];
#pragma unroll
            for (int i = 0; i < 8; i++)
#pragma unroll
                for (int j = 0; j < 8; j++)
                    acc[i][j] = fmaf(af[i], bf[j], acc[i][j]);
        }
        __syncthreads();
    }

#pragma unroll
    for (int i = 0; i < 8; i++) {
        int m = bm * 128 + ((i < 4) ? (ty << 2) + i : 64 + (ty << 2) + (i - 4));
#pragma unroll
        for (int jb = 0; jb < 2; jb++) {
            int n = bn * 128 + ((jb == 0) ? (tx << 2) : 64 + (tx << 2));
            float4 v;
            v.x = acc[i][jb * 4 + 0] + bias[n + 0];
            v.y = acc[i][jb * 4 + 1] + bias[n + 1];
            v.z = acc[i][jb * 4 + 2] + bias[n + 2];
            v.w = acc[i][jb * 4 + 3] + bias[n + 3];
            if (EPI == 0) {
                int which = n >> 9;   // 0=q 1=k 2=v
                int rem = n & 511;
                int h = rem >> 6;
                int dd = rem & 63;
                int b = m >> 12;
                int l = m & (L_ - 1);
                float* dst = (which == 0) ? g_q : (which == 1) ? g_k : g_v;
                *(float4*)(dst + ((((size_t)b * HEADS + h) * L_ + l) << 6) + dd) = v;
            } else {
                *(float4*)(C + (size_t)m * N + n) = v;
            }
        }
    }
}

// ============================================================
// Flash attention fp32: 64x64 Q-tile / block, 256 threads,
// 4x4 S and O fragments per thread, online softmax.
// smem: Qs[d][r] (4096f) | Vs[k][dd] (4096f) | KP[68-stride] union of
//       Ks[d][c] (S phase) and Ps[k][r] (PV phase)
// ============================================================
__global__ __launch_bounds__(256) void attn_kernel()
{
    extern __shared__ float sm[];
    float (*Qs)[64] = (float(*)[64])sm;
    float (*Vs)[64] = (float(*)[64])(sm + 4096);
    float (*KP)[68] = (float(*)[68])(sm + 8192);

    int tid = threadIdx.x;
    int tx = tid & 15, ty = tid >> 4;
    int tx4 = tx << 2, ty4 = ty << 2;

    int bh = blockIdx.x;                         // b*8 + h
    int qt = (int)gridDim.y - 1 - (int)blockIdx.y;  // heavy tiles first

    const float* Qg = g_q + ((size_t)bh * L_ + qt * 64) * HD;
    const float* Kg = g_k + (size_t)bh * L_ * HD;
    const float* Vg = g_v + (size_t)bh * L_ * HD;

    // Load Q transposed: Qs[d][r]
    {
        int r = tid & 63, c0 = (tid >> 6) << 4;
#pragma unroll
        for (int j = 0; j < 16; j += 4) {
            float4 v = *(const float4*)(Qg + r * 64 + c0 + j);
            Qs[c0 + j + 0][r] = v.x;
            Qs[c0 + j + 1][r] = v.y;
            Qs[c0 + j + 2][r] = v.z;
            Qs[c0 + j + 3][r] = v.w;
        }
    }

    float mrow[4], lrow[4], o[4][4];
#pragma unroll
    for (int i = 0; i < 4; i++) {
        mrow[i] = -1e30f;
        lrow[i] = 0.f;
#pragma unroll
        for (int j = 0; j < 4; j++) o[i][j] = 0.f;
    }

    const float scale = 0.125f;   // 1/sqrt(64)
    int rbase = qt * 64 + ty4;

    for (int kt = 0; kt <= qt; ++kt) {
        __syncthreads();  // prior PV reads done before overwriting smem
        // Load K transposed into KP, V natural into Vs
        {
            const float* Kt = Kg + (size_t)kt * 64 * 64;
            int r = tid & 63, c0 = (tid >> 6) << 4;
#pragma unroll
            for (int j = 0; j < 16; j += 4) {
                float4 v = *(const float4*)(Kt + r * 64 + c0 + j);
                KP[c0 + j + 0][r] = v.x;
                KP[c0 + j + 1][r] = v.y;
                KP[c0 + j + 2][r] = v.z;
                KP[c0 + j + 3][r] = v.w;
            }
            const float4* Vt = (const float4*)(Vg + (size_t)kt * 64 * 64);
            float4* Vd = (float4*)Vs;
#pragma unroll
            for (int w = 0; w < 4; w++) Vd[tid + 256 * w] = Vt[tid + 256 * w];
        }
        __syncthreads();

        // S = Q K^T (64x64 tile, 4x4 per thread)
        float s[4][4];
#pragma unroll
        for (int i = 0; i < 4; i++)
#pragma unroll
            for (int j = 0; j < 4; j++) s[i][j] = 0.f;

#pragma unroll 8
        for (int d = 0; d < 64; ++d) {
            float4 qv = *(const float4*)&Qs[d][ty4];
            float4 kv = *(const float4*)&KP[d][tx4];
            float qa[4] = {qv.x, qv.y, qv.z, qv.w};
            float ka[4] = {kv.x, kv.y, kv.z, kv.w};
#pragma unroll
            for (int i = 0; i < 4; i++)
#pragma unroll
                for (int j = 0; j < 4; j++)
                    s[i][j] = fmaf(qa[i], ka[j], s[i][j]);
        }

        // mask + scale + online softmax update
        int cb = kt * 64 + tx4;
        float p[4][4];
#pragma unroll
        for (int i = 0; i < 4; i++) {
            int r = rbase + i;
            float rm = -1e30f;
#pragma unroll
            for (int j = 0; j < 4; j++) {
                int c = cb + j;
                bool ok = (c <= r) && (c >= PREFIX || r < PREFIX);
                s[i][j] = ok ? s[i][j] * scale : -1e30f;
                rm = fmaxf(rm, s[i][j]);
            }
#pragma unroll
            for (int off = 8; off; off >>= 1)
                rm = fmaxf(rm, __shfl_xor_sync(0xffffffffu, rm, off, 16));
            float mn = fmaxf(mrow[i], rm);
            float alpha = __expf(mrow[i] - mn);
            float rs = 0.f;
#pragma unroll
            for (int j = 0; j < 4; j++) {
                p[i][j] = __expf(s[i][j] - mn);
                rs += p[i][j];
            }
#pragma unroll
            for (int off = 8; off; off >>= 1)
                rs += __shfl_xor_sync(0xffffffffu, rs, off, 16);
            lrow[i] = lrow[i] * alpha + rs;
            mrow[i] = mn;
#pragma unroll
            for (int j = 0; j < 4; j++) o[i][j] *= alpha;
        }

        __syncthreads();  // all KP(K) reads done before P overwrite
#pragma unroll
        for (int j = 0; j < 4; j++)
#pragma unroll
            for (int i = 0; i < 4; i++)
                KP[tx4 + j][ty4 + i] = p[i][j];   // Ps[k][r]
        __syncthreads();

        // O += P V
#pragma unroll 8
        for (int k = 0; k < 64; ++k) {
            float4 pv = *(const float4*)&KP[k][ty4];
            float4 vv = *(const float4*)&Vs[k][tx4];
            float pa[4] = {pv.x, pv.y, pv.z, pv.w};
            float va[4] = {vv.x, vv.y, vv.z, vv.w};
#pragma unroll
            for (int i = 0; i < 4; i++)
#pragma unroll
                for (int j = 0; j < 4; j++)
                    o[i][j] = fmaf(pa[i], va[j], o[i][j]);
        }
    }

    // Epilogue: ctx[b][l][h*64+dd] = O / l
    int b = bh >> 3, h = bh & 7;
#pragma unroll
    for (int i = 0; i < 4; i++) {
        float inv = 1.f / lrow[i];
        int l = qt * 64 + ty4 + i;
        float4 v;
        v.x = o[i][0] * inv;
        v.y = o[i][1] * inv;
        v.z = o[i][2] * inv;
        v.w = o[i][3] * inv;
        *(float4*)(g_ctx + ((size_t)(b * L_ + l)) * HIDDEN + h * 64 + tx4) = v;
    }
}

// ============================================================
extern "C" void kernel_launch(void* const* d_in, const int* in_sizes, int n_in,
                              void* d_out, int out_size)
{
    const float* x     = (const float*)d_in[0];
    const float* w_in  = (const float*)d_in[1];
    const float* b_in  = (const float*)d_in[2];
    const float* w_out = (const float*)d_in[3];
    const float* b_out = (const float*)d_in[4];
    float* out = (float*)d_out;

    // qkv = x @ w_in + b_in, scattered into g_q/g_k/g_v
    sgemm_kernel<0><<<dim3(12, 64), 256>>>(x, w_in, b_in, nullptr,
                                           M_ROWS, 3 * HIDDEN, HIDDEN);

    // attention
    const int ATTN_SMEM = (4096 + 4096 + 64 * 68) * 4;  // 50176 B
    cudaFuncSetAttribute(attn_kernel,
                         cudaFuncAttributeMaxDynamicSharedMemorySize, ATTN_SMEM);
    attn_kernel<<<dim3(16, 64), 256, ATTN_SMEM>>>();

    // out = ctx @ w_out + b_out
    sgemm_kernel<1><<<dim3(4, 64), 256>>>(nullptr, w_out, b_out, out,
                                          M_ROWS, HIDDEN, HIDDEN);
}

// round 2
// speedup vs baseline: 1.0298x; 1.0298x over previous
#include <cuda_runtime.h>

typedef unsigned long long ull;

#define B_      2
#define L_      4096
#define HIDDEN  512
#define HEADS   8
#define HD      64
#define PREFIX  1
#define M_ROWS  (B_ * L_)        // 8192

// Scratch (allocation-free rule: __device__ globals)
__device__ float g_q[B_ * HEADS * L_ * HD];
__device__ float g_k[B_ * HEADS * L_ * HD];
__device__ float g_v[B_ * HEADS * L_ * HD];
__device__ float g_ctx[B_ * L_ * HIDDEN];

// ---- packed fp32x2 helpers (Blackwell sm_103a) ----
__device__ __forceinline__ void ffma2(ull& d, ull a, ull b) {
    asm("fma.rn.f32x2 %0, %1, %2, %0;" : "+l"(d) : "l"(a), "l"(b));
}
__device__ __forceinline__ ull pack2(float x, float y) {
    ull r; asm("mov.b64 %0, {%1, %2};" : "=l"(r) : "f"(x), "f"(y)); return r;
}
__device__ __forceinline__ float2 unpack2(ull v) {
    float2 r; asm("mov.b64 {%0, %1}, %2;" : "=f"(r.x), "=f"(r.y) : "l"(v)); return r;
}
__device__ __forceinline__ ull mul2(ull a, ull b) {
    ull r; asm("mul.rn.f32x2 %0, %1, %2;" : "=l"(r) : "l"(a), "l"(b)); return r;
}

// ============================================================
// SGEMM 128x128x8, 256 threads, 8x8 per thread, f32x2 FMAs.
// Accumulators paired along rows (a-side pairs free from smem).
// EPI=0: C = A@B + bias scattered into g_q/g_k/g_v ([B,H,L,hd])
// EPI=1: C = g_ctx@B + bias stored plain row-major into C
// ============================================================
template <int EPI>
__global__ __launch_bounds__(256) void sgemm_kernel(
    const float* __restrict__ A_in, const float* __restrict__ B_in,
    const float* __restrict__ bias, float* __restrict__ C,
    int M, int N, int K)
{
    __shared__ float As[8][128];
    __shared__ float Bs[8][128];

    const float* A = (EPI == 1) ? (const float*)g_ctx : A_in;

    int tid = threadIdx.x;
    int tx = tid & 15, ty = tid >> 4;
    int tx4 = tx << 2, ty4 = ty << 2;
    int bm = blockIdx.y, bn = blockIdx.x;

    // acc[i2][j]: i2 pairs rows: i2<2 -> rows ty4+2*i2+{0,1}; i2>=2 -> 64+ty4+2*(i2-2)+{0,1}
    ull acc[4][8];
#pragma unroll
    for (int i = 0; i < 4; i++)
#pragma unroll
        for (int j = 0; j < 8; j++) acc[i][j] = 0ull;

    int arow = tid >> 1;
    int acol = (tid & 1) << 2;
    int brow = tid >> 5;
    int bcol = (tid & 31) << 2;

    const float* Ap = A + (size_t)(bm * 128 + arow) * K + acol;
    const float* Bp = B_in + (size_t)brow * N + bn * 128 + bcol;

    for (int kt = 0; kt < K; kt += 8) {
        float4 a4 = *(const float4*)(Ap + kt);
        float4 b4 = *(const float4*)(Bp + (size_t)kt * N);
        As[acol + 0][arow] = a4.x;
        As[acol + 1][arow] = a4.y;
        As[acol + 2][arow] = a4.z;
        As[acol + 3][arow] = a4.w;
        *(float4*)&Bs[brow][bcol] = b4;
        __syncthreads();

#pragma unroll
        for (int k = 0; k < 8; k++) {
            ull a2[4];
            a2[0] = *(const ull*)&As[k][ty4];
            a2[1] = *(const ull*)&As[k][ty4 + 2];
            a2[2] = *(const ull*)&As[k][64 + ty4];
            a2[3] = *(const ull*)&As[k][64 + ty4 + 2];
            float4 bl = *(const float4*)&Bs[k][tx4];
            float4 bh = *(const float4*)&Bs[k][64 + tx4];
            ull b2[8];
            b2[0] = pack2(bl.x, bl.x); b2[1] = pack2(bl.y, bl.y);
            b2[2] = pack2(bl.z, bl.z); b2[3] = pack2(bl.w, bl.w);
            b2[4] = pack2(bh.x, bh.x); b2[5] = pack2(bh.y, bh.y);
            b2[6] = pack2(bh.z, bh.z); b2[7] = pack2(bh.w, bh.w);
#pragma unroll
            for (int i = 0; i < 4; i++)
#pragma unroll
                for (int j = 0; j < 8; j++)
                    ffma2(acc[i][j], a2[i], b2[j]);
        }
        __syncthreads();
    }

    // unpack into old [i][j] layout: i = 2*i2 + part (0..3 first half, 4..7 second)
    float Cr[8][8];
#pragma unroll
    for (int i2 = 0; i2 < 4; i2++)
#pragma unroll
        for (int j = 0; j < 8; j++) {
            float2 v = unpack2(acc[i2][j]);
            Cr[2 * i2 + 0][j] = v.x;
            Cr[2 * i2 + 1][j] = v.y;
        }

#pragma unroll
    for (int i = 0; i < 8; i++) {
        int m = bm * 128 + ((i < 4) ? ty4 + i : 64 + ty4 + (i - 4));
#pragma unroll
        for (int jb = 0; jb < 2; jb++) {
            int n = bn * 128 + ((jb == 0) ? tx4 : 64 + tx4);
            float4 v;
            v.x = Cr[i][jb * 4 + 0] + bias[n + 0];
            v.y = Cr[i][jb * 4 + 1] + bias[n + 1];
            v.z = Cr[i][jb * 4 + 2] + bias[n + 2];
            v.w = Cr[i][jb * 4 + 3] + bias[n + 3];
            if (EPI == 0) {
                int which = n >> 9;   // 0=q 1=k 2=v
                int rem = n & 511;
                int h = rem >> 6;
                int dd = rem & 63;
                int b = m >> 12;
                int l = m & (L_ - 1);
                float* dst = (which == 0) ? g_q : (which == 1) ? g_k : g_v;
                *(float4*)(dst + ((((size_t)b * HEADS + h) * L_ + l) << 6) + dd) = v;
            } else {
                *(float4*)(C + (size_t)m * N + n) = v;
            }
        }
    }
}

// ============================================================
// Flash attention fp32 (f32x2 FMAs): 64x64 Q-tile / block,
// 256 threads, 4x4 frags (rows paired), online softmax.
// smem: Qs[d][r] (4096f) | Vs[k][dd] (4096f) | KP[68-stride] union
// ============================================================
__global__ __launch_bounds__(256) void attn_kernel()
{
    extern __shared__ float sm[];
    float (*Qs)[64] = (float(*)[64])sm;
    float (*Vs)[64] = (float(*)[64])(sm + 4096);
    float (*KP)[68] = (float(*)[68])(sm + 8192);

    int tid = threadIdx.x;
    int tx = tid & 15, ty = tid >> 4;
    int tx4 = tx << 2, ty4 = ty << 2;

    int bh = blockIdx.x;                            // b*8 + h
    int qt = (int)gridDim.y - 1 - (int)blockIdx.y;  // heavy tiles first

    const float* Qg = g_q + ((size_t)bh * L_ + qt * 64) * HD;
    const float* Kg = g_k + (size_t)bh * L_ * HD;
    const float* Vg = g_v + (size_t)bh * L_ * HD;

    // Load Q transposed: Qs[d][r]
    {
        int r = tid & 63, c0 = (tid >> 6) << 4;
#pragma unroll
        for (int j = 0; j < 16; j += 4) {
            float4 v = *(const float4*)(Qg + r * 64 + c0 + j);
            Qs[c0 + j + 0][r] = v.x;
            Qs[c0 + j + 1][r] = v.y;
            Qs[c0 + j + 2][r] = v.z;
            Qs[c0 + j + 3][r] = v.w;
        }
    }

    float mrow[4], lrow[4];
    ull o2[2][4];   // rows paired: o2[i2][j] = {o[2i2][j], o[2i2+1][j]}
#pragma unroll
    for (int i = 0; i < 4; i++) { mrow[i] = -1e30f; lrow[i] = 0.f; }
#pragma unroll
    for (int i = 0; i < 2; i++)
#pragma unroll
        for (int j = 0; j < 4; j++) o2[i][j] = 0ull;

    const float scale = 0.125f;   // 1/sqrt(64)
    int rbase = qt * 64 + ty4;

    for (int kt = 0; kt <= qt; ++kt) {
        __syncthreads();  // prior PV reads done before overwriting smem
        // Load K transposed into KP, V natural into Vs
        {
            const float* Kt = Kg + (size_t)kt * 64 * 64;
            int r = tid & 63, c0 = (tid >> 6) << 4;
#pragma unroll
            for (int j = 0; j < 16; j += 4) {
                float4 v = *(const float4*)(Kt + r * 64 + c0 + j);
                KP[c0 + j + 0][r] = v.x;
                KP[c0 + j + 1][r] = v.y;
                KP[c0 + j + 2][r] = v.z;
                KP[c0 + j + 3][r] = v.w;
            }
            const float4* Vt = (const float4*)(Vg + (size_t)kt * 64 * 64);
            float4* Vd = (float4*)Vs;
#pragma unroll
            for (int w = 0; w < 4; w++) Vd[tid + 256 * w] = Vt[tid + 256 * w];
        }
        __syncthreads();

        // S = Q K^T (64x64 tile, 4x4 per thread, rows paired)
        ull s2[2][4];
#pragma unroll
        for (int i = 0; i < 2; i++)
#pragma unroll
            for (int j = 0; j < 4; j++) s2[i][j] = 0ull;

#pragma unroll 8
        for (int d = 0; d < 64; ++d) {
            ull qa0 = *(const ull*)&Qs[d][ty4];
            ull qa1 = *(const ull*)&Qs[d][ty4 + 2];
            float4 kv = *(const float4*)&KP[d][tx4];
            ull kb0 = pack2(kv.x, kv.x);
            ull kb1 = pack2(kv.y, kv.y);
            ull kb2 = pack2(kv.z, kv.z);
            ull kb3 = pack2(kv.w, kv.w);
            ffma2(s2[0][0], qa0, kb0); ffma2(s2[0][1], qa0, kb1);
            ffma2(s2[0][2], qa0, kb2); ffma2(s2[0][3], qa0, kb3);
            ffma2(s2[1][0], qa1, kb0); ffma2(s2[1][1], qa1, kb1);
            ffma2(s2[1][2], qa1, kb2); ffma2(s2[1][3], qa1, kb3);
        }

        // unpack S
        float s[4][4];
#pragma unroll
        for (int i2 = 0; i2 < 2; i2++)
#pragma unroll
            for (int j = 0; j < 4; j++) {
                float2 v = unpack2(s2[i2][j]);
                s[2 * i2 + 0][j] = v.x;
                s[2 * i2 + 1][j] = v.y;
            }

        // mask + scale + online softmax update
        int cb = kt * 64 + tx4;
        float p[4][4], alpha[4];
#pragma unroll
        for (int i = 0; i < 4; i++) {
            int r = rbase + i;
            float rm = -1e30f;
#pragma unroll
            for (int j = 0; j < 4; j++) {
                int c = cb + j;
                bool ok = (c <= r) && (c >= PREFIX || r < PREFIX);
                s[i][j] = ok ? s[i][j] * scale : -1e30f;
                rm = fmaxf(rm, s[i][j]);
            }
#pragma unroll
            for (int off = 8; off; off >>= 1)
                rm = fmaxf(rm, __shfl_xor_sync(0xffffffffu, rm, off, 16));
            float mn = fmaxf(mrow[i], rm);
            alpha[i] = __expf(mrow[i] - mn);
            float rs = 0.f;
#pragma unroll
            for (int j = 0; j < 4; j++) {
                p[i][j] = __expf(s[i][j] - mn);
                rs += p[i][j];
            }
#pragma unroll
            for (int off = 8; off; off >>= 1)
                rs += __shfl_xor_sync(0xffffffffu, rs, off, 16);
            lrow[i] = lrow[i] * alpha[i] + rs;
            mrow[i] = mn;
        }
        // O *= alpha (rows paired)
        {
            ull al0 = pack2(alpha[0], alpha[1]);
            ull al1 = pack2(alpha[2], alpha[3]);
#pragma unroll
            for (int j = 0; j < 4; j++) {
                o2[0][j] = mul2(o2[0][j], al0);
                o2[1][j] = mul2(o2[1][j], al1);
            }
        }

        __syncthreads();  // all KP(K) reads done before P overwrite
#pragma unroll
        for (int j = 0; j < 4; j++) {
            float4 pv;
            pv.x = p[0][j]; pv.y = p[1][j]; pv.z = p[2][j]; pv.w = p[3][j];
            *(float4*)&KP[tx4 + j][ty4] = pv;   // Ps[k][r]
        }
        __syncthreads();

        // O += P V (rows paired)
#pragma unroll 8
        for (int k = 0; k < 64; ++k) {
            ull pa0 = *(const ull*)&KP[k][ty4];
            ull pa1 = *(const ull*)&KP[k][ty4 + 2];
            float4 vv = *(const float4*)&Vs[k][tx4];
            ull vb0 = pack2(vv.x, vv.x);
            ull vb1 = pack2(vv.y, vv.y);
            ull vb2 = pack2(vv.z, vv.z);
            ull vb3 = pack2(vv.w, vv.w);
            ffma2(o2[0][0], pa0, vb0); ffma2(o2[0][1], pa0, vb1);
            ffma2(o2[0][2], pa0, vb2); ffma2(o2[0][3], pa0, vb3);
            ffma2(o2[1][0], pa1, vb0); ffma2(o2[1][1], pa1, vb1);
            ffma2(o2[1][2], pa1, vb2); ffma2(o2[1][3], pa1, vb3);
        }
    }

    // Epilogue: ctx[b][l][h*64+dd] = O / l
    int b = bh >> 3, h = bh & 7;
    float o[4][4];
#pragma unroll
    for (int i2 = 0; i2 < 2; i2++)
#pragma unroll
        for (int j = 0; j < 4; j++) {
            float2 v = unpack2(o2[i2][j]);
            o[2 * i2 + 0][j] = v.x;
            o[2 * i2 + 1][j] = v.y;
        }
#pragma unroll
    for (int i = 0; i < 4; i++) {
        float inv = 1.f / lrow[i];
        int l = qt * 64 + ty4 + i;
        float4 v;
        v.x = o[i][0] * inv;
        v.y = o[i][1] * inv;
        v.z = o[i][2] * inv;
        v.w = o[i][3] * inv;
        *(float4*)(g_ctx + ((size_t)(b * L_ + l)) * HIDDEN + h * 64 + tx4) = v;
    }
}

// ============================================================
extern "C" void kernel_launch(void* const* d_in, const int* in_sizes, int n_in,
                              void* d_out, int out_size)
{
    const float* x     = (const float*)d_in[0];
    const float* w_in  = (const float*)d_in[1];
    const float* b_in  = (const float*)d_in[2];
    const float* w_out = (const float*)d_in[3];
    const float* b_out = (const float*)d_in[4];
    float* out = (float*)d_out;

    // qkv = x @ w_in + b_in, scattered into g_q/g_k/g_v
    sgemm_kernel<0><<<dim3(12, 64), 256>>>(x, w_in, b_in, nullptr,
                                           M_ROWS, 3 * HIDDEN, HIDDEN);

    // attention
    const int ATTN_SMEM = (4096 + 4096 + 64 * 68) * 4;  // 50176 B
    cudaFuncSetAttribute(attn_kernel,
                         cudaFuncAttributeMaxDynamicSharedMemorySize, ATTN_SMEM);
    attn_kernel<<<dim3(16, 64), 256, ATTN_SMEM>>>();

    // out = ctx @ w_out + b_out
    sgemm_kernel<1><<<dim3(4, 64), 256>>>(nullptr, w_out, b_out, out,
                                          M_ROWS, HIDDEN, HIDDEN);
}

// round 4
// speedup vs baseline: 1.8153x; 1.7629x over previous
#include <cuda_runtime.h>
#include <cstdint>

typedef unsigned long long ull;

#define B_      2
#define L_      4096
#define HIDDEN  512
#define HEADS   8
#define HD      64
#define PREFIX  1
#define M_ROWS  (B_ * L_)        // 8192

// Scratch (allocation-free rule: __device__ globals)
__device__ float g_q[B_ * HEADS * L_ * HD];
__device__ float g_k[B_ * HEADS * L_ * HD];
__device__ float g_v[B_ * HEADS * L_ * HD];
__device__ float g_ctx[B_ * L_ * HIDDEN];

// ============================================================
// helpers
// ============================================================
__device__ __forceinline__ uint32_t smem_u32(const void* p) {
    uint32_t a;
    asm("{ .reg .u64 t; cvta.to.shared.u64 t, %1; cvt.u32.u64 %0, t; }" : "=r"(a) : "l"(p));
    return a;
}
__device__ __forceinline__ uint32_t f2u(float x) { return __float_as_uint(x); }
// [lo16(a)=hi16 of a | hi16(b)] -> bf16x2 with a in low half (truncation split)
__device__ __forceinline__ uint32_t prmt_hi16(uint32_t a, uint32_t b) {
    uint32_t r; asm("prmt.b32 %0,%1,%2,0x7632;" : "=r"(r) : "r"(a), "r"(b)); return r;
}
// pack {lo, hi} floats into bf16x2 (lo -> low half), round-to-nearest
__device__ __forceinline__ uint32_t cvt_bf16x2(float lo, float hi) {
    uint32_t r; asm("cvt.rn.bf16x2.f32 %0,%1,%2;" : "=r"(r) : "f"(hi), "f"(lo)); return r;
}
__device__ __forceinline__ float ex2f(float x) {
    float r; asm("ex2.approx.f32 %0,%1;" : "=f"(r) : "f"(x)); return r;
}
__device__ __forceinline__ uint32_t swz128(uint32_t o) { return o ^ ((o >> 3) & 0x70u); }

__device__ __forceinline__ void ldsm4(uint32_t& r0, uint32_t& r1, uint32_t& r2, uint32_t& r3,
                                      uint32_t addr) {
    asm volatile("ldmatrix.sync.aligned.m8n8.x4.shared.b16 {%0,%1,%2,%3}, [%4];"
                 : "=r"(r0), "=r"(r1), "=r"(r2), "=r"(r3) : "r"(addr));
}
__device__ __forceinline__ void ldsm4t(uint32_t& r0, uint32_t& r1, uint32_t& r2, uint32_t& r3,
                                       uint32_t addr) {
    asm volatile("ldmatrix.sync.aligned.m8n8.x4.trans.shared.b16 {%0,%1,%2,%3}, [%4];"
                 : "=r"(r0), "=r"(r1), "=r"(r2), "=r"(r3) : "r"(addr));
}
__device__ __forceinline__ void mma_bf16(float* c, const uint32_t* a, uint32_t b0, uint32_t b1) {
    asm volatile(
        "mma.sync.aligned.m16n8k16.row.col.f32.bf16.bf16.f32 "
        "{%0,%1,%2,%3},{%4,%5,%6,%7},{%8,%9},{%0,%1,%2,%3};"
        : "+f"(c[0]), "+f"(c[1]), "+f"(c[2]), "+f"(c[3])
        : "r"(a[0]), "r"(a[1]), "r"(a[2]), "r"(a[3]), "r"(b0), "r"(b1));
}

// convert 8 consecutive floats -> bf16-hi uint4 + bf16-lo uint4
__device__ __forceinline__ void cvt8(const float* v, uint4& H, uint4& Lw) {
    uint32_t hw[4], lw[4];
#pragma unroll
    for (int j = 0; j < 4; j++) {
        uint32_t b0 = f2u(v[2 * j]), b1 = f2u(v[2 * j + 1]);
        hw[j] = prmt_hi16(b0, b1);
        float h0 = __uint_as_float(b0 & 0xffff0000u);
        float h1 = __uint_as_float(b1 & 0xffff0000u);
        lw[j] = cvt_bf16x2(v[2 * j] - h0, v[2 * j + 1] - h1);
    }
    H  = make_uint4(hw[0], hw[1], hw[2], hw[3]);
    Lw = make_uint4(lw[0], lw[1], lw[2], lw[3]);
}

// convert half a 64-float row (4 of 8 16B-groups), store swizzled (128B rows)
__device__ __forceinline__ void cvt_store_half(const float4* g4, char* smp,
                                               uint32_t hioff, uint32_t looff,
                                               int row, int g0) {
    uint32_t rb = (uint32_t)row * 128u;
#pragma unroll
    for (int gi = 0; gi < 4; gi++) {
        int gix = g0 + gi;
        float4 x0 = g4[2 * gix], x1 = g4[2 * gix + 1];
        float v[8] = {x0.x, x0.y, x0.z, x0.w, x1.x, x1.y, x1.z, x1.w};
        uint4 H, Lw;
        cvt8(v, H, Lw);
        uint32_t a = swz128(rb + (uint32_t)gix * 16u);
        *(uint4*)(smp + hioff + a) = H;
        *(uint4*)(smp + looff + a) = Lw;
    }
}

// ============================================================
// SMEM layout (bytes): Q 128x64 bf16 hi/lo, K/V 64x64 bf16 hi/lo
// ============================================================
#define SQHI 0u
#define SQLO 16384u
#define SKHI 32768u
#define SKLO 40960u
#define SVHI 49152u
#define SVLO 57344u
#define ATTN_SMEM 65536

// ============================================================
// Flash attention via mma.sync bf16x3, unnormalized softmax.
// 256 threads = 8 warps; warp w owns q-rows [16w,16w+16); key tiles of 64.
// ============================================================
__global__ __launch_bounds__(256, 1) void attn_mma_kernel()
{
    extern __shared__ char smp[];
    const uint32_t sbase = smem_u32(smp);
    int tid = threadIdx.x;
    int w = tid >> 5, lane = tid & 31;

    int bh = blockIdx.x;                            // b*8 + h
    int qt = (int)gridDim.y - 1 - (int)blockIdx.y;  // heavy tiles first
    int nkt = 2 * qt + 2;                           // 64-key tiles

    const float* Qg = g_q + ((size_t)bh * L_ + (size_t)qt * 128) * HD;
    const float* Kg = g_k + (size_t)bh * L_ * HD;
    const float* Vg = g_v + (size_t)bh * L_ * HD;

    // Prologue: load Q (128 rows, 2 threads/row)
    {
        int row = tid >> 1, g0 = (tid & 1) * 4;
        cvt_store_half((const float4*)(Qg + (size_t)row * 64), smp, SQHI, SQLO, row, g0);
    }
    __syncthreads();

    // Q A-fragments, resident whole kernel: qh/ql[ks][4]
    uint32_t qh[4][4], ql[4][4];
    {
        int arow = 16 * w + (lane & 15);
#pragma unroll
        for (int ks = 0; ks < 4; ks++) {
            int cb = ks * 32 + ((lane & 16) ? 16 : 0);
            uint32_t off = swz128((uint32_t)arow * 128u + (uint32_t)cb);
            ldsm4(qh[ks][0], qh[ks][1], qh[ks][2], qh[ks][3], sbase + SQHI + off);
            ldsm4(ql[ks][0], ql[ks][1], ql[ks][2], ql[ks][3], sbase + SQLO + off);
        }
    }

    float oc[8][4];
#pragma unroll
    for (int n = 0; n < 8; n++)
#pragma unroll
        for (int j = 0; j < 4; j++) oc[n][j] = 0.f;
    float lsum0 = 0.f, lsum1 = 0.f;

    const float Cc = 0.18033688011112042f;  // (1/8) * log2(e)
    int row0 = qt * 128 + 16 * w + (lane >> 2);
    int row1 = row0 + 8;

    for (int kt = 0; kt < nkt; ++kt) {
        __syncthreads();   // previous iteration's smem reads done
        // load K,V tile (bf16 split): 128 threads each
        if (tid < 128) {
            int row = tid >> 1, g0 = (tid & 1) * 4;
            const float* kr = Kg + ((size_t)kt * 64 + row) * 64;
            cvt_store_half((const float4*)kr, smp, SKHI, SKLO, row, g0);
        } else {
            int t = tid - 128;
            int row = t >> 1, g0 = (t & 1) * 4;
            const float* vr = Vg + ((size_t)kt * 64 + row) * 64;
            cvt_store_half((const float4*)vr, smp, SVHI, SVLO, row, g0);
        }
        __syncthreads();

        // ---- S = Q K^T : 16x64 per warp ----
        float sc[8][4];
#pragma unroll
        for (int n = 0; n < 8; n++)
#pragma unroll
            for (int j = 0; j < 4; j++) sc[n][j] = 0.f;

#pragma unroll
        for (int ks = 0; ks < 4; ks++) {
#pragma unroll
            for (int np = 0; np < 4; np++) {
                int key = np * 16 + (lane & 7) + ((lane & 16) ? 8 : 0);
                int db = ks * 32 + ((lane & 8) ? 16 : 0);
                uint32_t off = swz128((uint32_t)key * 128u + (uint32_t)db);
                uint32_t h0, h1, h2, h3, l0, l1, l2, l3;
                ldsm4(h0, h1, h2, h3, sbase + SKHI + off);
                ldsm4(l0, l1, l2, l3, sbase + SKLO + off);
                mma_bf16(sc[2 * np],     qh[ks], h0, h1);
                mma_bf16(sc[2 * np],     qh[ks], l0, l1);
                mma_bf16(sc[2 * np],     ql[ks], h0, h1);
                mma_bf16(sc[2 * np + 1], qh[ks], h2, h3);
                mma_bf16(sc[2 * np + 1], qh[ks], l2, l3);
                mma_bf16(sc[2 * np + 1], ql[ks], h2, h3);
            }
        }

        // ---- softmax (unnormalized) ----
        bool edge = (kt == 0) || (kt >= 2 * qt);
        int colb = kt * 64 + 2 * (lane & 3);
#pragma unroll
        for (int n = 0; n < 8; n++) {
            float e0 = ex2f(sc[n][0] * Cc);
            float e1 = ex2f(sc[n][1] * Cc);
            float e2 = ex2f(sc[n][2] * Cc);
            float e3 = ex2f(sc[n][3] * Cc);
            if (edge) {
                int c0 = colb + 8 * n, c1 = c0 + 1;
                bool k00 = (c0 <= row0) && (c0 >= PREFIX || row0 < PREFIX);
                bool k01 = (c1 <= row0) && (c1 >= PREFIX || row0 < PREFIX);
                bool k10 = (c0 <= row1) && (c0 >= PREFIX || row1 < PREFIX);
                bool k11 = (c1 <= row1) && (c1 >= PREFIX || row1 < PREFIX);
                e0 = k00 ? e0 : 0.f;
                e1 = k01 ? e1 : 0.f;
                e2 = k10 ? e2 : 0.f;
                e3 = k11 ? e3 : 0.f;
            }
            sc[n][0] = e0; sc[n][1] = e1; sc[n][2] = e2; sc[n][3] = e3;
            lsum0 += e0 + e1;
            lsum1 += e2 + e3;
        }

        // ---- O += P V : P C-frags -> A-frags in registers ----
#pragma unroll
        for (int t = 0; t < 4; t++) {
            uint32_t ph[4], pl[4];
            {
                float* cA = sc[2 * t];
                float* cB = sc[2 * t + 1];
                uint32_t a0 = f2u(cA[0]), a1 = f2u(cA[1]);
                uint32_t a2 = f2u(cA[2]), a3 = f2u(cA[3]);
                uint32_t b0 = f2u(cB[0]), b1 = f2u(cB[1]);
                uint32_t b2 = f2u(cB[2]), b3 = f2u(cB[3]);
                ph[0] = prmt_hi16(a0, a1);
                ph[1] = prmt_hi16(a2, a3);
                ph[2] = prmt_hi16(b0, b1);
                ph[3] = prmt_hi16(b2, b3);
                pl[0] = cvt_bf16x2(cA[0] - __uint_as_float(a0 & 0xffff0000u),
                                   cA[1] - __uint_as_float(a1 & 0xffff0000u));
                pl[1] = cvt_bf16x2(cA[2] - __uint_as_float(a2 & 0xffff0000u),
                                   cA[3] - __uint_as_float(a3 & 0xffff0000u));
                pl[2] = cvt_bf16x2(cB[0] - __uint_as_float(b0 & 0xffff0000u),
                                   cB[1] - __uint_as_float(b1 & 0xffff0000u));
                pl[3] = cvt_bf16x2(cB[2] - __uint_as_float(b2 & 0xffff0000u),
                                   cB[3] - __uint_as_float(b3 & 0xffff0000u));
            }
            int key = t * 16 + (lane & 7) + ((lane & 8) ? 8 : 0);
#pragma unroll
            for (int dp = 0; dp < 4; dp++) {
                int db = dp * 32 + ((lane & 16) ? 16 : 0);
                uint32_t off = swz128((uint32_t)key * 128u + (uint32_t)db);
                uint32_t h0, h1, h2, h3, l0, l1, l2, l3;
                ldsm4t(h0, h1, h2, h3, sbase + SVHI + off);
                ldsm4t(l0, l1, l2, l3, sbase + SVLO + off);
                mma_bf16(oc[2 * dp],     ph, h0, h1);
                mma_bf16(oc[2 * dp],     ph, l0, l1);
                mma_bf16(oc[2 * dp],     pl, h0, h1);
                mma_bf16(oc[2 * dp + 1], ph, h2, h3);
                mma_bf16(oc[2 * dp + 1], ph, l2, l3);
                mma_bf16(oc[2 * dp + 1], pl, h2, h3);
            }
        }
    }

    // lane reduction of lsum (rows live in lanes sharing lane>>2)
    lsum0 += __shfl_xor_sync(0xffffffffu, lsum0, 1);
    lsum0 += __shfl_xor_sync(0xffffffffu, lsum0, 2);
    lsum1 += __shfl_xor_sync(0xffffffffu, lsum1, 1);
    lsum1 += __shfl_xor_sync(0xffffffffu, lsum1, 2);
    float inv0 = 1.f / lsum0, inv1 = 1.f / lsum1;

    // store: ctx[b][row][h*64+d]
    int b = bh >> 3, h = bh & 7;
    float* d0p = g_ctx + (size_t)(b * L_ + row0) * HIDDEN + h * 64;
    float* d1p = g_ctx + (size_t)(b * L_ + row1) * HIDDEN + h * 64;
#pragma unroll
    for (int n = 0; n < 8; n++) {
        int d = 8 * n + 2 * (lane & 3);
        float2 v0 = make_float2(oc[n][0] * inv0, oc[n][1] * inv0);
        float2 v1 = make_float2(oc[n][2] * inv1, oc[n][3] * inv1);
        *(float2*)(d0p + d) = v0;
        *(float2*)(d1p + d) = v1;
    }
}

// ============================================================
// SGEMM 128x128x8 (fp32, unchanged)
// ============================================================
template <int EPI>
__global__ __launch_bounds__(256) void sgemm_kernel(
    const float* __restrict__ A_in, const float* __restrict__ B_in,
    const float* __restrict__ bias, float* __restrict__ C,
    int M, int N, int K)
{
    __shared__ float As[8][128];
    __shared__ float Bs[8][128];

    const float* A = (EPI == 1) ? (const float*)g_ctx : A_in;

    int tid = threadIdx.x;
    int tx = tid & 15, ty = tid >> 4;
    int tx4 = tx << 2, ty4 = ty << 2;
    int bm = blockIdx.y, bn = blockIdx.x;

    float acc[8][8];
#pragma unroll
    for (int i = 0; i < 8; i++)
#pragma unroll
        for (int j = 0; j < 8; j++) acc[i][j] = 0.f;

    int arow = tid >> 1;
    int acol = (tid & 1) << 2;
    int brow = tid >> 5;
    int bcol = (tid & 31) << 2;

    const float* Ap = A + (size_t)(bm * 128 + arow) * K + acol;
    const float* Bp = B_in + (size_t)brow * N + bn * 128 + bcol;

    for (int kt = 0; kt < K; kt += 8) {
        float4 a4 = *(const float4*)(Ap + kt);
        float4 b4 = *(const float4*)(Bp + (size_t)kt * N);
        As[acol + 0][arow] = a4.x;
        As[acol + 1][arow] = a4.y;
        As[acol + 2][arow] = a4.z;
        As[acol + 3][arow] = a4.w;
        *(float4*)&Bs[brow][bcol] = b4;
        __syncthreads();

#pragma unroll
        for (int k = 0; k < 8; k++) {
            float af[8], bf[8];
            *(float4*)&af[0] = *(const float4*)&As[k][ty4];
            *(float4*)&af[4] = *(const float4*)&As[k][64 + ty4];
            *(float4*)&bf[0] = *(const float4*)&Bs[k][tx4];
            *(float4*)&bf[4] = *(const float4*)&Bs[k][64 + tx4];
#pragma unroll
            for (int i = 0; i < 8; i++)
#pragma unroll
                for (int j = 0; j < 8; j++)
                    acc[i][j] = fmaf(af[i], bf[j], acc[i][j]);
        }
        __syncthreads();
    }

#pragma unroll
    for (int i = 0; i < 8; i++) {
        int m = bm * 128 + ((i < 4) ? ty4 + i : 64 + ty4 + (i - 4));
#pragma unroll
        for (int jb = 0; jb < 2; jb++) {
            int n = bn * 128 + ((jb == 0) ? tx4 : 64 + tx4);
            float4 v;
            v.x = acc[i][jb * 4 + 0] + bias[n + 0];
            v.y = acc[i][jb * 4 + 1] + bias[n + 1];
            v.z = acc[i][jb * 4 + 2] + bias[n + 2];
            v.w = acc[i][jb * 4 + 3] + bias[n + 3];
            if (EPI == 0) {
                int which = n >> 9;   // 0=q 1=k 2=v
                int rem = n & 511;
                int h = rem >> 6;
                int dd = rem & 63;
                int b = m >> 12;
                int l = m & (L_ - 1);
                float* dst = (which == 0) ? g_q : (which == 1) ? g_k : g_v;
                *(float4*)(dst + ((((size_t)b * HEADS + h) * L_ + l) << 6) + dd) = v;
            } else {
                *(float4*)(C + (size_t)m * N + n) = v;
            }
        }
    }
}

// ============================================================
extern "C" void kernel_launch(void* const* d_in, const int* in_sizes, int n_in,
                              void* d_out, int out_size)
{
    const float* x     = (const float*)d_in[0];
    const float* w_in  = (const float*)d_in[1];
    const float* b_in  = (const float*)d_in[2];
    const float* w_out = (const float*)d_in[3];
    const float* b_out = (const float*)d_in[4];
    float* out = (float*)d_out;

    // qkv = x @ w_in + b_in, scattered into g_q/g_k/g_v
    sgemm_kernel<0><<<dim3(12, 64), 256>>>(x, w_in, b_in, nullptr,
                                           M_ROWS, 3 * HIDDEN, HIDDEN);

    // attention (mma.sync bf16x3, unnormalized softmax)
    cudaFuncSetAttribute(attn_mma_kernel,
                         cudaFuncAttributeMaxDynamicSharedMemorySize, ATTN_SMEM);
    attn_mma_kernel<<<dim3(16, 32), 256, ATTN_SMEM>>>();

    // out = ctx @ w_out + b_out
    sgemm_kernel<1><<<dim3(4, 64), 256>>>(nullptr, w_out, b_out, out,
                                          M_ROWS, HIDDEN, HIDDEN);
}

// round 5
// speedup vs baseline: 2.5155x; 1.3857x over previous
#include <cuda_runtime.h>
#include <cstdint>

typedef unsigned long long ull;

#define B_      2
#define L_      4096
#define HIDDEN  512
#define HEADS   8
#define HD      64
#define PREFIX  1
#define M_ROWS  (B_ * L_)        // 8192

// ---- bf16 hi/lo split storage (allocation-free: __device__ globals) ----
__device__ __align__(16) uint16_t gx_hi[M_ROWS * HIDDEN],  gx_lo[M_ROWS * HIDDEN];
__device__ __align__(16) uint16_t gwi_hi[3 * HIDDEN * HIDDEN], gwi_lo[3 * HIDDEN * HIDDEN];
__device__ __align__(16) uint16_t gwo_hi[HIDDEN * HIDDEN], gwo_lo[HIDDEN * HIDDEN];
__device__ __align__(16) uint16_t gq_hi[M_ROWS * HIDDEN],  gq_lo[M_ROWS * HIDDEN];
__device__ __align__(16) uint16_t gk_hi[M_ROWS * HIDDEN],  gk_lo[M_ROWS * HIDDEN];
__device__ __align__(16) uint16_t gv_hi[M_ROWS * HIDDEN],  gv_lo[M_ROWS * HIDDEN];
__device__ __align__(16) uint16_t gctx_hi[M_ROWS * HIDDEN], gctx_lo[M_ROWS * HIDDEN];

// ============================================================
// helpers
// ============================================================
__device__ __forceinline__ uint32_t smem_u32(const void* p) {
    uint32_t a;
    asm("{ .reg .u64 t; cvta.to.shared.u64 t, %1; cvt.u32.u64 %0, t; }" : "=r"(a) : "l"(p));
    return a;
}
__device__ __forceinline__ uint32_t f2u(float x) { return __float_as_uint(x); }
// low half = hi16(a) (bf16-trunc of a), high half = hi16(b)
__device__ __forceinline__ uint32_t prmt_hi16(uint32_t a, uint32_t b) {
    uint32_t r; asm("prmt.b32 %0,%1,%2,0x7632;" : "=r"(r) : "r"(a), "r"(b)); return r;
}
// pack {lo, hi} floats into bf16x2 (first arg -> low half), round-to-nearest
__device__ __forceinline__ uint32_t cvt_bf16x2(float lo, float hi) {
    uint32_t r; asm("cvt.rn.bf16x2.f32 %0,%1,%2;" : "=r"(r) : "f"(hi), "f"(lo)); return r;
}
__device__ __forceinline__ uint16_t bf16_rn(float x) {
    uint16_t u; asm("cvt.rn.bf16.f32 %0,%1;" : "=h"(u) : "f"(x)); return u;
}
__device__ __forceinline__ float ex2f(float x) {
    float r; asm("ex2.approx.f32 %0,%1;" : "=f"(r) : "f"(x)); return r;
}
__device__ __forceinline__ uint32_t swz128(uint32_t o) { return o ^ ((o >> 3) & 0x70u); }

__device__ __forceinline__ void ldsm4(uint32_t& r0, uint32_t& r1, uint32_t& r2, uint32_t& r3,
                                      uint32_t addr) {
    asm volatile("ldmatrix.sync.aligned.m8n8.x4.shared.b16 {%0,%1,%2,%3}, [%4];"
                 : "=r"(r0), "=r"(r1), "=r"(r2), "=r"(r3) : "r"(addr));
}
__device__ __forceinline__ void ldsm4t(uint32_t& r0, uint32_t& r1, uint32_t& r2, uint32_t& r3,
                                       uint32_t addr) {
    asm volatile("ldmatrix.sync.aligned.m8n8.x4.trans.shared.b16 {%0,%1,%2,%3}, [%4];"
                 : "=r"(r0), "=r"(r1), "=r"(r2), "=r"(r3) : "r"(addr));
}
__device__ __forceinline__ void mma_bf16(float* c, const uint32_t* a, uint32_t b0, uint32_t b1) {
    asm volatile(
        "mma.sync.aligned.m16n8k16.row.col.f32.bf16.bf16.f32 "
        "{%0,%1,%2,%3},{%4,%5,%6,%7},{%8,%9},{%0,%1,%2,%3};"
        : "+f"(c[0]), "+f"(c[1]), "+f"(c[2]), "+f"(c[3])
        : "r"(a[0]), "r"(a[1]), "r"(a[2]), "r"(a[3]), "r"(b0), "r"(b1));
}

// ============================================================
// conversion kernels: fp32 -> bf16 hi/lo split
// ============================================================
__global__ __launch_bounds__(256) void conv_x_kernel(const float* __restrict__ x)
{
    size_t gid = (size_t)blockIdx.x * 256 + threadIdx.x;
    size_t i = gid * 4;
    float4 v = *(const float4*)(x + i);
    uint32_t bx = f2u(v.x), by = f2u(v.y), bz = f2u(v.z), bw = f2u(v.w);
    uint2 H, Lw;
    H.x = prmt_hi16(bx, by);
    H.y = prmt_hi16(bz, bw);
    Lw.x = cvt_bf16x2(v.x - __uint_as_float(bx & 0xffff0000u),
                      v.y - __uint_as_float(by & 0xffff0000u));
    Lw.y = cvt_bf16x2(v.z - __uint_as_float(bz & 0xffff0000u),
                      v.w - __uint_as_float(bw & 0xffff0000u));
    *(uint2*)(gx_hi + i) = H;
    *(uint2*)(gx_lo + i) = Lw;
}

// transpose+split: w [K, N] fp32 -> wT [N, K] bf16 hi/lo. which: 0=w_in, 1=w_out
__global__ __launch_bounds__(256) void conv_wT_kernel(const float* __restrict__ w,
                                                      int K, int N, int which)
{
    __shared__ float t[32][33];
    uint16_t* dh = which ? gwo_hi : gwi_hi;
    uint16_t* dl = which ? gwo_lo : gwi_lo;
    int n0 = blockIdx.x * 32, k0 = blockIdx.y * 32;
    int tx = threadIdx.x & 31, ty = threadIdx.x >> 5;
#pragma unroll
    for (int i = 0; i < 4; i++)
        t[ty + 8 * i][tx] = w[(size_t)(k0 + ty + 8 * i) * N + n0 + tx];
    __syncthreads();
#pragma unroll
    for (int i = 0; i < 4; i++) {
        int nn = ty + 8 * i;
        float v = t[tx][nn];
        uint32_t b = f2u(v);
        size_t idx = (size_t)(n0 + nn) * K + k0 + tx;
        dh[idx] = (uint16_t)(b >> 16);
        dl[idx] = bf16_rn(v - __uint_as_float(b & 0xffff0000u));
    }
}

// ============================================================
// GEMM bf16x3 via mma.sync: C[M,N] = A[M,512] @ B^T[N,512] + bias
// MODE 0: A=x, B=w_inT,  epilogue -> q/k/v bf16 hi/lo (head-major)
// MODE 1: A=ctx, B=w_outT, epilogue -> fp32 Cout
// Block: 256 thr, tile 128x128, k-chunk 64, double-buffered smem (128KB).
// Warp w: wm=w&1 (64 rows), wn=w>>1 (32 cols).
// ============================================================
template <int MODE>
__global__ __launch_bounds__(256, 1) void gemm_bf16_kernel(
    const float* __restrict__ bias, float* __restrict__ Cout)
{
    extern __shared__ char smp[];
    const uint32_t sbase = smem_u32(smp);
    int tid = threadIdx.x;
    int lane = tid & 31, w = tid >> 5;
    int wm = w & 1, wn = w >> 1;
    int bm = blockIdx.y, bn = blockIdx.x;

    const uint16_t* Ahi = (MODE == 0) ? gx_hi : gctx_hi;
    const uint16_t* Alo = (MODE == 0) ? gx_lo : gctx_lo;
    const uint16_t* Bhi = (MODE == 0) ? gwi_hi : gwo_hi;
    const uint16_t* Blo = (MODE == 0) ? gwi_lo : gwo_lo;

    int r = tid >> 1, g0 = (tid & 1) * 4;
    size_t aoff = (size_t)(bm * 128 + r) * HIDDEN;
    size_t boff = (size_t)(bn * 128 + r) * HIDDEN;

    float acc[4][4][4];
#pragma unroll
    for (int i = 0; i < 4; i++)
#pragma unroll
        for (int j = 0; j < 4; j++)
#pragma unroll
            for (int e = 0; e < 4; e++) acc[i][j][e] = 0.f;

    // smem buffer: buf*65536 + {AHI 0, ALO 16K, BHI 32K, BLO 48K}
#define LOAD_CHUNK(kc, buf) do {                                              \
        char* dst = smp + (uint32_t)(buf) * 65536u;                           \
        const uint4* ah = (const uint4*)(Ahi + aoff + (kc) * 64);             \
        const uint4* al = (const uint4*)(Alo + aoff + (kc) * 64);             \
        const uint4* bh = (const uint4*)(Bhi + boff + (kc) * 64);             \
        const uint4* bl = (const uint4*)(Blo + boff + (kc) * 64);             \
        _Pragma("unroll")                                                     \
        for (int i = 0; i < 4; i++) {                                         \
            uint32_t so = swz128((uint32_t)r * 128u + (uint32_t)(g0 + i) * 16u); \
            *(uint4*)(dst + so)          = ah[g0 + i];                        \
            *(uint4*)(dst + 16384 + so)  = al[g0 + i];                        \
            *(uint4*)(dst + 32768 + so)  = bh[g0 + i];                        \
            *(uint4*)(dst + 49152 + so)  = bl[g0 + i];                        \
        }                                                                     \
    } while (0)

    LOAD_CHUNK(0, 0);
    __syncthreads();

    const int NK = HIDDEN / 64;   // 8
    for (int kc = 0; kc < NK; kc++) {
        if (kc + 1 < NK) LOAD_CHUNK(kc + 1, (kc + 1) & 1);

        uint32_t abase = sbase + (uint32_t)(kc & 1) * 65536u;
        uint32_t bbase = abase + 32768u;
#pragma unroll
        for (int ks = 0; ks < 4; ks++) {
            uint32_t ah[4][4], al[4][4];
#pragma unroll
            for (int mi = 0; mi < 4; mi++) {
                uint32_t off = swz128((uint32_t)(wm * 64 + mi * 16 + (lane & 15)) * 128u
                                      + (uint32_t)(ks * 32 + ((lane & 16) ? 16 : 0)));
                ldsm4(ah[mi][0], ah[mi][1], ah[mi][2], ah[mi][3], abase + off);
                ldsm4(al[mi][0], al[mi][1], al[mi][2], al[mi][3], abase + 16384u + off);
            }
#pragma unroll
            for (int np = 0; np < 2; np++) {
                uint32_t boffs = swz128((uint32_t)(wn * 32 + np * 16 + (lane & 7)
                                                   + ((lane & 16) ? 8 : 0)) * 128u
                                        + (uint32_t)(ks * 32 + ((lane & 8) ? 16 : 0)));
                uint32_t h0, h1, h2, h3, l0, l1, l2, l3;
                ldsm4(h0, h1, h2, h3, bbase + boffs);
                ldsm4(l0, l1, l2, l3, bbase + 16384u + boffs);
#pragma unroll
                for (int mi = 0; mi < 4; mi++) {
                    mma_bf16(acc[mi][2 * np],     ah[mi], h0, h1);
                    mma_bf16(acc[mi][2 * np],     ah[mi], l0, l1);
                    mma_bf16(acc[mi][2 * np],     al[mi], h0, h1);
                    mma_bf16(acc[mi][2 * np + 1], ah[mi], h2, h3);
                    mma_bf16(acc[mi][2 * np + 1], ah[mi], l2, l3);
                    mma_bf16(acc[mi][2 * np + 1], al[mi], h2, h3);
                }
            }
        }
        __syncthreads();
    }
#undef LOAD_CHUNK

    // ---- epilogue ----
#pragma unroll
    for (int mi = 0; mi < 4; mi++) {
        int r0 = bm * 128 + wm * 64 + mi * 16 + (lane >> 2);
#pragma unroll
        for (int nj = 0; nj < 4; nj++) {
            int c0 = bn * 128 + wn * 32 + nj * 8 + 2 * (lane & 3);
            float bb0 = __ldg(bias + c0), bb1 = __ldg(bias + c0 + 1);
            float v0 = acc[mi][nj][0] + bb0, v1 = acc[mi][nj][1] + bb1;
            float v2 = acc[mi][nj][2] + bb0, v3 = acc[mi][nj][3] + bb1;
            if (MODE == 0) {
                int which = c0 >> 9, h = (c0 >> 6) & 7, d = c0 & 63;
                uint16_t* dh = (which == 0) ? gq_hi : (which == 1) ? gk_hi : gv_hi;
                uint16_t* dl = (which == 0) ? gq_lo : (which == 1) ? gk_lo : gv_lo;
                int b = r0 >> 12;
                size_t base0 = ((size_t)((b * 8 + h) * L_ + (r0 & 4095))) * 64 + d;
                size_t base1 = base0 + 8 * 64;
                uint32_t u0 = f2u(v0), u1 = f2u(v1), u2 = f2u(v2), u3 = f2u(v3);
                *(uint32_t*)(dh + base0) = prmt_hi16(u0, u1);
                *(uint32_t*)(dl + base0) =
                    cvt_bf16x2(v0 - __uint_as_float(u0 & 0xffff0000u),
                               v1 - __uint_as_float(u1 & 0xffff0000u));
                *(uint32_t*)(dh + base1) = prmt_hi16(u2, u3);
                *(uint32_t*)(dl + base1) =
                    cvt_bf16x2(v2 - __uint_as_float(u2 & 0xffff0000u),
                               v3 - __uint_as_float(u3 & 0xffff0000u));
            } else {
                *(float2*)(Cout + (size_t)r0 * HIDDEN + c0) = make_float2(v0, v1);
                *(float2*)(Cout + (size_t)(r0 + 8) * HIDDEN + c0) = make_float2(v2, v3);
            }
        }
    }
}

// ============================================================
// SMEM layout for attention (bytes)
// ============================================================
#define SQHI 0u
#define SQLO 16384u
#define SKHI 32768u
#define SKLO 40960u
#define SVHI 49152u
#define SVLO 57344u
#define ATTN_SMEM 65536

// ============================================================
// Flash attention via mma.sync bf16x3, unnormalized softmax.
// Inputs already bf16 hi/lo -> inner loop is pure swizzled copy.
// 256 threads = 8 warps; warp w owns q-rows [16w,16w+16); key tiles of 64.
// ============================================================
__global__ __launch_bounds__(256, 1) void attn_mma_kernel()
{
    extern __shared__ char smp[];
    const uint32_t sbase = smem_u32(smp);
    int tid = threadIdx.x;
    int w = tid >> 5, lane = tid & 31;

    int bh = blockIdx.x;                            // b*8 + h
    int qt = (int)gridDim.y - 1 - (int)blockIdx.y;  // heavy tiles first
    int nkt = 2 * qt + 2;                           // 64-key tiles

    // Prologue: copy Q tile (128 rows x 128B hi + lo)
    {
        int rr = tid >> 1, g0 = (tid & 1) * 4;
        const uint4* qh4 = (const uint4*)(gq_hi + ((size_t)bh * L_ + (size_t)qt * 128 + rr) * 64);
        const uint4* ql4 = (const uint4*)(gq_lo + ((size_t)bh * L_ + (size_t)qt * 128 + rr) * 64);
#pragma unroll
        for (int i = 0; i < 4; i++) {
            uint32_t so = swz128((uint32_t)rr * 128u + (uint32_t)(g0 + i) * 16u);
            *(uint4*)(smp + SQHI + so) = qh4[g0 + i];
            *(uint4*)(smp + SQLO + so) = ql4[g0 + i];
        }
    }
    __syncthreads();

    // Q A-fragments resident for the whole kernel
    uint32_t qh[4][4], ql[4][4];
    {
        int arow = 16 * w + (lane & 15);
#pragma unroll
        for (int ks = 0; ks < 4; ks++) {
            uint32_t off = swz128((uint32_t)arow * 128u
                                  + (uint32_t)(ks * 32 + ((lane & 16) ? 16 : 0)));
            ldsm4(qh[ks][0], qh[ks][1], qh[ks][2], qh[ks][3], sbase + SQHI + off);
            ldsm4(ql[ks][0], ql[ks][1], ql[ks][2], ql[ks][3], sbase + SQLO + off);
        }
    }

    float oc[8][4];
#pragma unroll
    for (int n = 0; n < 8; n++)
#pragma unroll
        for (int j = 0; j < 4; j++) oc[n][j] = 0.f;
    float lsum0 = 0.f, lsum1 = 0.f;

    const float Cc = 0.18033688011112042f;  // (1/8) * log2(e)
    int row0 = qt * 128 + 16 * w + (lane >> 2);
    int row1 = row0 + 8;

    for (int kt = 0; kt < nkt; ++kt) {
        __syncthreads();   // previous iteration's smem reads done
        if (tid < 128) {   // K tile copy
            int rr = tid >> 1, g0 = (tid & 1) * 4;
            size_t src = ((size_t)bh * L_ + (size_t)kt * 64 + rr) * 64;
            const uint4* kh4 = (const uint4*)(gk_hi + src);
            const uint4* kl4 = (const uint4*)(gk_lo + src);
#pragma unroll
            for (int i = 0; i < 4; i++) {
                uint32_t so = swz128((uint32_t)rr * 128u + (uint32_t)(g0 + i) * 16u);
                *(uint4*)(smp + SKHI + so) = kh4[g0 + i];
                *(uint4*)(smp + SKLO + so) = kl4[g0 + i];
            }
        } else {           // V tile copy
            int t = tid - 128;
            int rr = t >> 1, g0 = (t & 1) * 4;
            size_t src = ((size_t)bh * L_ + (size_t)kt * 64 + rr) * 64;
            const uint4* vh4 = (const uint4*)(gv_hi + src);
            const uint4* vl4 = (const uint4*)(gv_lo + src);
#pragma unroll
            for (int i = 0; i < 4; i++) {
                uint32_t so = swz128((uint32_t)rr * 128u + (uint32_t)(g0 + i) * 16u);
                *(uint4*)(smp + SVHI + so) = vh4[g0 + i];
                *(uint4*)(smp + SVLO + so) = vl4[g0 + i];
            }
        }
        __syncthreads();

        // ---- S = Q K^T : 16x64 per warp ----
        float sc[8][4];
#pragma unroll
        for (int n = 0; n < 8; n++)
#pragma unroll
            for (int j = 0; j < 4; j++) sc[n][j] = 0.f;

#pragma unroll
        for (int ks = 0; ks < 4; ks++) {
#pragma unroll
            for (int np = 0; np < 4; np++) {
                int key = np * 16 + (lane & 7) + ((lane & 16) ? 8 : 0);
                uint32_t off = swz128((uint32_t)key * 128u
                                      + (uint32_t)(ks * 32 + ((lane & 8) ? 16 : 0)));
                uint32_t h0, h1, h2, h3, l0, l1, l2, l3;
                ldsm4(h0, h1, h2, h3, sbase + SKHI + off);
                ldsm4(l0, l1, l2, l3, sbase + SKLO + off);
                mma_bf16(sc[2 * np],     qh[ks], h0, h1);
                mma_bf16(sc[2 * np],     qh[ks], l0, l1);
                mma_bf16(sc[2 * np],     ql[ks], h0, h1);
                mma_bf16(sc[2 * np + 1], qh[ks], h2, h3);
                mma_bf16(sc[2 * np + 1], qh[ks], l2, l3);
                mma_bf16(sc[2 * np + 1], ql[ks], h2, h3);
            }
        }

        // ---- softmax (unnormalized) ----
        bool edge = (kt == 0) || (kt >= 2 * qt);
        int colb = kt * 64 + 2 * (lane & 3);
#pragma unroll
        for (int n = 0; n < 8; n++) {
            float e0 = ex2f(sc[n][0] * Cc);
            float e1 = ex2f(sc[n][1] * Cc);
            float e2 = ex2f(sc[n][2] * Cc);
            float e3 = ex2f(sc[n][3] * Cc);
            if (edge) {
                int c0 = colb + 8 * n, c1 = c0 + 1;
                bool k00 = (c0 <= row0) && (c0 >= PREFIX || row0 < PREFIX);
                bool k01 = (c1 <= row0) && (c1 >= PREFIX || row0 < PREFIX);
                bool k10 = (c0 <= row1) && (c0 >= PREFIX || row1 < PREFIX);
                bool k11 = (c1 <= row1) && (c1 >= PREFIX || row1 < PREFIX);
                e0 = k00 ? e0 : 0.f;
                e1 = k01 ? e1 : 0.f;
                e2 = k10 ? e2 : 0.f;
                e3 = k11 ? e3 : 0.f;
            }
            sc[n][0] = e0; sc[n][1] = e1; sc[n][2] = e2; sc[n][3] = e3;
            lsum0 += e0 + e1;
            lsum1 += e2 + e3;
        }

        // ---- O += P V : P C-frags -> A-frags in registers ----
#pragma unroll
        for (int t = 0; t < 4; t++) {
            uint32_t ph[4], pl[4];
            {
                float* cA = sc[2 * t];
                float* cB = sc[2 * t + 1];
                uint32_t a0 = f2u(cA[0]), a1 = f2u(cA[1]);
                uint32_t a2 = f2u(cA[2]), a3 = f2u(cA[3]);
                uint32_t b0 = f2u(cB[0]), b1 = f2u(cB[1]);
                uint32_t b2 = f2u(cB[2]), b3 = f2u(cB[3]);
                ph[0] = prmt_hi16(a0, a1);
                ph[1] = prmt_hi16(a2, a3);
                ph[2] = prmt_hi16(b0, b1);
                ph[3] = prmt_hi16(b2, b3);
                pl[0] = cvt_bf16x2(cA[0] - __uint_as_float(a0 & 0xffff0000u),
                                   cA[1] - __uint_as_float(a1 & 0xffff0000u));
                pl[1] = cvt_bf16x2(cA[2] - __uint_as_float(a2 & 0xffff0000u),
                                   cA[3] - __uint_as_float(a3 & 0xffff0000u));
                pl[2] = cvt_bf16x2(cB[0] - __uint_as_float(b0 & 0xffff0000u),
                                   cB[1] - __uint_as_float(b1 & 0xffff0000u));
                pl[3] = cvt_bf16x2(cB[2] - __uint_as_float(b2 & 0xffff0000u),
                                   cB[3] - __uint_as_float(b3 & 0xffff0000u));
            }
            int key = t * 16 + (lane & 7) + ((lane & 8) ? 8 : 0);
#pragma unroll
            for (int dp = 0; dp < 4; dp++) {
                uint32_t off = swz128((uint32_t)key * 128u
                                      + (uint32_t)(dp * 32 + ((lane & 16) ? 16 : 0)));
                uint32_t h0, h1, h2, h3, l0, l1, l2, l3;
                ldsm4t(h0, h1, h2, h3, sbase + SVHI + off);
                ldsm4t(l0, l1, l2, l3, sbase + SVLO + off);
                mma_bf16(oc[2 * dp],     ph, h0, h1);
                mma_bf16(oc[2 * dp],     ph, l0, l1);
                mma_bf16(oc[2 * dp],     pl, h0, h1);
                mma_bf16(oc[2 * dp + 1], ph, h2, h3);
                mma_bf16(oc[2 * dp + 1], ph, l2, l3);
                mma_bf16(oc[2 * dp + 1], pl, h2, h3);
            }
        }
    }

    // lane reduction of lsum (rows live in lanes sharing lane>>2)
    lsum0 += __shfl_xor_sync(0xffffffffu, lsum0, 1);
    lsum0 += __shfl_xor_sync(0xffffffffu, lsum0, 2);
    lsum1 += __shfl_xor_sync(0xffffffffu, lsum1, 1);
    lsum1 += __shfl_xor_sync(0xffffffffu, lsum1, 2);
    float inv0 = 1.f / lsum0, inv1 = 1.f / lsum1;

    // store ctx as bf16 hi/lo: ctx[b][row][h*64+d]
    int b = bh >> 3, h = bh & 7;
    size_t r0base = (size_t)(b * L_ + row0) * HIDDEN + h * 64;
    size_t r1base = (size_t)(b * L_ + row1) * HIDDEN + h * 64;
#pragma unroll
    for (int n = 0; n < 8; n++) {
        int d = 8 * n + 2 * (lane & 3);
        float v0 = oc[n][0] * inv0, v1 = oc[n][1] * inv0;
        float v2 = oc[n][2] * inv1, v3 = oc[n][3] * inv1;
        uint32_t u0 = f2u(v0), u1 = f2u(v1), u2 = f2u(v2), u3 = f2u(v3);
        *(uint32_t*)(gctx_hi + r0base + d) = prmt_hi16(u0, u1);
        *(uint32_t*)(gctx_lo + r0base + d) =
            cvt_bf16x2(v0 - __uint_as_float(u0 & 0xffff0000u),
                       v1 - __uint_as_float(u1 & 0xffff0000u));
        *(uint32_t*)(gctx_hi + r1base + d) = prmt_hi16(u2, u3);
        *(uint32_t*)(gctx_lo + r1base + d) =
            cvt_bf16x2(v2 - __uint_as_float(u2 & 0xffff0000u),
                       v3 - __uint_as_float(u3 & 0xffff0000u));
    }
}

// ============================================================
extern "C" void kernel_launch(void* const* d_in, const int* in_sizes, int n_in,
                              void* d_out, int out_size)
{
    const float* x     = (const float*)d_in[0];
    const float* w_in  = (const float*)d_in[1];
    const float* b_in  = (const float*)d_in[2];
    const float* w_out = (const float*)d_in[3];
    const float* b_out = (const float*)d_in[4];
    float* out = (float*)d_out;

    // fp32 -> bf16 hi/lo splits
    conv_x_kernel<<<(M_ROWS * HIDDEN / 4) / 256, 256>>>(x);
    conv_wT_kernel<<<dim3(3 * HIDDEN / 32, HIDDEN / 32), 256>>>(w_in, HIDDEN, 3 * HIDDEN, 0);
    conv_wT_kernel<<<dim3(HIDDEN / 32, HIDDEN / 32), 256>>>(w_out, HIDDEN, HIDDEN, 1);

    // qkv = x @ w_in + b_in  -> q/k/v bf16 hi/lo
    cudaFuncSetAttribute(gemm_bf16_kernel<0>,
                         cudaFuncAttributeMaxDynamicSharedMemorySize, 131072);
    gemm_bf16_kernel<0><<<dim3(12, 64), 256, 131072>>>(b_in, nullptr);

    // attention
    cudaFuncSetAttribute(attn_mma_kernel,
                         cudaFuncAttributeMaxDynamicSharedMemorySize, ATTN_SMEM);
    attn_mma_kernel<<<dim3(16, 32), 256, ATTN_SMEM>>>();

    // out = ctx @ w_out + b_out (fp32 output)
    cudaFuncSetAttribute(gemm_bf16_kernel<1>,
                         cudaFuncAttributeMaxDynamicSharedMemorySize, 131072);
    gemm_bf16_kernel<1><<<dim3(4, 64), 256, 131072>>>(b_out, out);
}

// round 6
// speedup vs baseline: 2.8711x; 1.1413x over previous
#include <cuda_runtime.h>
#include <cstdint>

typedef unsigned long long ull;

#define B_      2
#define L_      4096
#define HIDDEN  512
#define HEADS   8
#define HD      64
#define PREFIX  1
#define M_ROWS  (B_ * L_)        // 8192

// ---- bf16 hi/lo split storage (allocation-free: __device__ globals) ----
__device__ __align__(16) uint16_t gx_hi[M_ROWS * HIDDEN],  gx_lo[M_ROWS * HIDDEN];
__device__ __align__(16) uint16_t gwi_hi[3 * HIDDEN * HIDDEN], gwi_lo[3 * HIDDEN * HIDDEN];
__device__ __align__(16) uint16_t gwo_hi[HIDDEN * HIDDEN], gwo_lo[HIDDEN * HIDDEN];
__device__ __align__(16) uint16_t gq_hi[M_ROWS * HIDDEN],  gq_lo[M_ROWS * HIDDEN];
__device__ __align__(16) uint16_t gk_hi[M_ROWS * HIDDEN],  gk_lo[M_ROWS * HIDDEN];
__device__ __align__(16) uint16_t gv_hi[M_ROWS * HIDDEN],  gv_lo[M_ROWS * HIDDEN];
__device__ __align__(16) uint16_t gctx_hi[M_ROWS * HIDDEN], gctx_lo[M_ROWS * HIDDEN];

// ============================================================
// helpers
// ============================================================
__device__ __forceinline__ uint32_t smem_u32(const void* p) {
    uint32_t a;
    asm("{ .reg .u64 t; cvta.to.shared.u64 t, %1; cvt.u32.u64 %0, t; }" : "=r"(a) : "l"(p));
    return a;
}
__device__ __forceinline__ uint32_t f2u(float x) { return __float_as_uint(x); }
__device__ __forceinline__ uint32_t prmt_hi16(uint32_t a, uint32_t b) {
    uint32_t r; asm("prmt.b32 %0,%1,%2,0x7632;" : "=r"(r) : "r"(a), "r"(b)); return r;
}
__device__ __forceinline__ uint32_t cvt_bf16x2(float lo, float hi) {
    uint32_t r; asm("cvt.rn.bf16x2.f32 %0,%1,%2;" : "=r"(r) : "f"(hi), "f"(lo)); return r;
}
__device__ __forceinline__ uint16_t bf16_rn(float x) {
    uint16_t u; asm("cvt.rn.bf16.f32 %0,%1;" : "=h"(u) : "f"(x)); return u;
}
__device__ __forceinline__ float ex2f(float x) {
    float r; asm("ex2.approx.f32 %0,%1;" : "=f"(r) : "f"(x)); return r;
}
__device__ __forceinline__ uint32_t swz128(uint32_t o) { return o ^ ((o >> 3) & 0x70u); }

__device__ __forceinline__ void cp16(uint32_t dst, const void* src) {
    asm volatile("cp.async.cg.shared.global [%0], [%1], 16;" :: "r"(dst), "l"(src) : "memory");
}
__device__ __forceinline__ void cp_commit() {
    asm volatile("cp.async.commit_group;" ::: "memory");
}
template <int N> __device__ __forceinline__ void cp_wait() {
    asm volatile("cp.async.wait_group %0;" :: "n"(N) : "memory");
}

__device__ __forceinline__ void ldsm4(uint32_t& r0, uint32_t& r1, uint32_t& r2, uint32_t& r3,
                                      uint32_t addr) {
    asm volatile("ldmatrix.sync.aligned.m8n8.x4.shared.b16 {%0,%1,%2,%3}, [%4];"
                 : "=r"(r0), "=r"(r1), "=r"(r2), "=r"(r3) : "r"(addr));
}
__device__ __forceinline__ void ldsm4t(uint32_t& r0, uint32_t& r1, uint32_t& r2, uint32_t& r3,
                                       uint32_t addr) {
    asm volatile("ldmatrix.sync.aligned.m8n8.x4.trans.shared.b16 {%0,%1,%2,%3}, [%4];"
                 : "=r"(r0), "=r"(r1), "=r"(r2), "=r"(r3) : "r"(addr));
}
__device__ __forceinline__ void mma_bf16(float* c, const uint32_t* a, uint32_t b0, uint32_t b1) {
    asm volatile(
        "mma.sync.aligned.m16n8k16.row.col.f32.bf16.bf16.f32 "
        "{%0,%1,%2,%3},{%4,%5,%6,%7},{%8,%9},{%0,%1,%2,%3};"
        : "+f"(c[0]), "+f"(c[1]), "+f"(c[2]), "+f"(c[3])
        : "r"(a[0]), "r"(a[1]), "r"(a[2]), "r"(a[3]), "r"(b0), "r"(b1));
}

// ============================================================
// conversion kernels: fp32 -> bf16 hi/lo split
// ============================================================
__global__ __launch_bounds__(256) void conv_x_kernel(const float* __restrict__ x)
{
    size_t gid = (size_t)blockIdx.x * 256 + threadIdx.x;
    size_t i = gid * 4;
    float4 v = *(const float4*)(x + i);
    uint32_t bx = f2u(v.x), by = f2u(v.y), bz = f2u(v.z), bw = f2u(v.w);
    uint2 H, Lw;
    H.x = prmt_hi16(bx, by);
    H.y = prmt_hi16(bz, bw);
    Lw.x = cvt_bf16x2(v.x - __uint_as_float(bx & 0xffff0000u),
                      v.y - __uint_as_float(by & 0xffff0000u));
    Lw.y = cvt_bf16x2(v.z - __uint_as_float(bz & 0xffff0000u),
                      v.w - __uint_as_float(bw & 0xffff0000u));
    *(uint2*)(gx_hi + i) = H;
    *(uint2*)(gx_lo + i) = Lw;
}

__global__ __launch_bounds__(256) void conv_wT_kernel(const float* __restrict__ w,
                                                      int K, int N, int which)
{
    __shared__ float t[32][33];
    uint16_t* dh = which ? gwo_hi : gwi_hi;
    uint16_t* dl = which ? gwo_lo : gwi_lo;
    int n0 = blockIdx.x * 32, k0 = blockIdx.y * 32;
    int tx = threadIdx.x & 31, ty = threadIdx.x >> 5;
#pragma unroll
    for (int i = 0; i < 4; i++)
        t[ty + 8 * i][tx] = w[(size_t)(k0 + ty + 8 * i) * N + n0 + tx];
    __syncthreads();
#pragma unroll
    for (int i = 0; i < 4; i++) {
        int nn = ty + 8 * i;
        float v = t[tx][nn];
        uint32_t b = f2u(v);
        size_t idx = (size_t)(n0 + nn) * K + k0 + tx;
        dh[idx] = (uint16_t)(b >> 16);
        dl[idx] = bf16_rn(v - __uint_as_float(b & 0xffff0000u));
    }
}

// ============================================================
// GEMM bf16x3 via mma.sync + cp.async 2-stage pipeline.
// C[M,N] = A[M,512] @ B^T[N,512] + bias
// MODE 0: A=x, B=w_inT,  epilogue -> q/k/v bf16 hi/lo (head-major)
// MODE 1: A=ctx, B=w_outT, epilogue -> fp32 Cout
// ============================================================
template <int MODE>
__global__ __launch_bounds__(256, 1) void gemm_bf16_kernel(
    const float* __restrict__ bias, float* __restrict__ Cout)
{
    extern __shared__ char smp[];
    const uint32_t sbase = smem_u32(smp);
    int tid = threadIdx.x;
    int lane = tid & 31, w = tid >> 5;
    int wm = w & 1, wn = w >> 1;
    int bm = blockIdx.y, bn = blockIdx.x;

    const uint16_t* Ahi = (MODE == 0) ? gx_hi : gctx_hi;
    const uint16_t* Alo = (MODE == 0) ? gx_lo : gctx_lo;
    const uint16_t* Bhi = (MODE == 0) ? gwi_hi : gwo_hi;
    const uint16_t* Blo = (MODE == 0) ? gwi_lo : gwo_lo;

    int r = tid >> 1, g0 = (tid & 1) * 4;
    size_t aoff = (size_t)(bm * 128 + r) * HIDDEN;
    size_t boff = (size_t)(bn * 128 + r) * HIDDEN;

    float acc[4][4][4];
#pragma unroll
    for (int i = 0; i < 4; i++)
#pragma unroll
        for (int j = 0; j < 4; j++)
#pragma unroll
            for (int e = 0; e < 4; e++) acc[i][j][e] = 0.f;

    // stage layout (64KB): {AHI 0, ALO 16K, BHI 32K, BLO 48K}; stage s at s*65536
#define ISSUE_CHUNK(kc, buf) do {                                              \
        uint32_t dst = sbase + (uint32_t)(buf) * 65536u;                        \
        const uint16_t* ah = Ahi + aoff + (kc) * 64;                            \
        const uint16_t* al = Alo + aoff + (kc) * 64;                            \
        const uint16_t* bh = Bhi + boff + (kc) * 64;                            \
        const uint16_t* bl = Blo + boff + (kc) * 64;                            \
        _Pragma("unroll")                                                       \
        for (int i = 0; i < 4; i++) {                                           \
            uint32_t so = swz128((uint32_t)r * 128u + (uint32_t)(g0 + i) * 16u);\
            cp16(dst + so,           ah + (g0 + i) * 8);                        \
            cp16(dst + 16384u + so,  al + (g0 + i) * 8);                        \
            cp16(dst + 32768u + so,  bh + (g0 + i) * 8);                        \
            cp16(dst + 49152u + so,  bl + (g0 + i) * 8);                        \
        }                                                                       \
        cp_commit();                                                            \
    } while (0)

    ISSUE_CHUNK(0, 0);

    const int NK = HIDDEN / 64;   // 8
    for (int kc = 0; kc < NK; kc++) {
        if (kc + 1 < NK) {
            ISSUE_CHUNK(kc + 1, (kc + 1) & 1);
            cp_wait<1>();
        } else {
            cp_wait<0>();
        }
        __syncthreads();

        uint32_t abase = sbase + (uint32_t)(kc & 1) * 65536u;
        uint32_t bbase = abase + 32768u;
#pragma unroll
        for (int ks = 0; ks < 4; ks++) {
            uint32_t ah[4][4], al[4][4];
#pragma unroll
            for (int mi = 0; mi < 4; mi++) {
                uint32_t off = swz128((uint32_t)(wm * 64 + mi * 16 + (lane & 15)) * 128u
                                      + (uint32_t)(ks * 32 + ((lane & 16) ? 16 : 0)));
                ldsm4(ah[mi][0], ah[mi][1], ah[mi][2], ah[mi][3], abase + off);
                ldsm4(al[mi][0], al[mi][1], al[mi][2], al[mi][3], abase + 16384u + off);
            }
#pragma unroll
            for (int np = 0; np < 2; np++) {
                uint32_t boffs = swz128((uint32_t)(wn * 32 + np * 16 + (lane & 7)
                                                   + ((lane & 16) ? 8 : 0)) * 128u
                                        + (uint32_t)(ks * 32 + ((lane & 8) ? 16 : 0)));
                uint32_t h0, h1, h2, h3, l0, l1, l2, l3;
                ldsm4(h0, h1, h2, h3, bbase + boffs);
                ldsm4(l0, l1, l2, l3, bbase + 16384u + boffs);
#pragma unroll
                for (int mi = 0; mi < 4; mi++) {
                    mma_bf16(acc[mi][2 * np],     ah[mi], h0, h1);
                    mma_bf16(acc[mi][2 * np],     ah[mi], l0, l1);
                    mma_bf16(acc[mi][2 * np],     al[mi], h0, h1);
                    mma_bf16(acc[mi][2 * np + 1], ah[mi], h2, h3);
                    mma_bf16(acc[mi][2 * np + 1], ah[mi], l2, l3);
                    mma_bf16(acc[mi][2 * np + 1], al[mi], h2, h3);
                }
            }
        }
        __syncthreads();
    }
#undef ISSUE_CHUNK

    // ---- epilogue ----
#pragma unroll
    for (int mi = 0; mi < 4; mi++) {
        int r0 = bm * 128 + wm * 64 + mi * 16 + (lane >> 2);
#pragma unroll
        for (int nj = 0; nj < 4; nj++) {
            int c0 = bn * 128 + wn * 32 + nj * 8 + 2 * (lane & 3);
            float bb0 = __ldg(bias + c0), bb1 = __ldg(bias + c0 + 1);
            float v0 = acc[mi][nj][0] + bb0, v1 = acc[mi][nj][1] + bb1;
            float v2 = acc[mi][nj][2] + bb0, v3 = acc[mi][nj][3] + bb1;
            if (MODE == 0) {
                int which = c0 >> 9, h = (c0 >> 6) & 7, d = c0 & 63;
                uint16_t* dh = (which == 0) ? gq_hi : (which == 1) ? gk_hi : gv_hi;
                uint16_t* dl = (which == 0) ? gq_lo : (which == 1) ? gk_lo : gv_lo;
                int b = r0 >> 12;
                size_t base0 = ((size_t)((b * 8 + h) * L_ + (r0 & 4095))) * 64 + d;
                size_t base1 = base0 + 8 * 64;
                uint32_t u0 = f2u(v0), u1 = f2u(v1), u2 = f2u(v2), u3 = f2u(v3);
                *(uint32_t*)(dh + base0) = prmt_hi16(u0, u1);
                *(uint32_t*)(dl + base0) =
                    cvt_bf16x2(v0 - __uint_as_float(u0 & 0xffff0000u),
                               v1 - __uint_as_float(u1 & 0xffff0000u));
                *(uint32_t*)(dh + base1) = prmt_hi16(u2, u3);
                *(uint32_t*)(dl + base1) =
                    cvt_bf16x2(v2 - __uint_as_float(u2 & 0xffff0000u),
                               v3 - __uint_as_float(u3 & 0xffff0000u));
            } else {
                *(float2*)(Cout + (size_t)r0 * HIDDEN + c0) = make_float2(v0, v1);
                *(float2*)(Cout + (size_t)(r0 + 8) * HIDDEN + c0) = make_float2(v2, v3);
            }
        }
    }
}

// ============================================================
// Attention SMEM: Q 32KB; K/V double buffer: buf s at 32K+s*32K,
// within buf: {KHI 0, KLO 8K, VHI 16K, VLO 24K}. Total 96KB.
// ============================================================
#define SQHI 0u
#define SQLO 16384u
#define SKV0 32768u
#define ATTN_SMEM 98304

// ============================================================
// Flash attention via mma.sync bf16x3, unnormalized softmax,
// cp.async double-buffered K/V tiles.
// ============================================================
__global__ __launch_bounds__(256, 1) void attn_mma_kernel()
{
    extern __shared__ char smp[];
    const uint32_t sbase = smem_u32(smp);
    int tid = threadIdx.x;
    int w = tid >> 5, lane = tid & 31;

    int bh = blockIdx.x;                            // b*8 + h
    int qt = (int)gridDim.y - 1 - (int)blockIdx.y;  // heavy tiles first
    int nkt = 2 * qt + 2;                           // 64-key tiles

    // per-thread K/V copy coords (K: tid<128, V: tid>=128)
    int ct = tid & 127;
    int rr = ct >> 1, g0 = (ct & 1) * 4;
    const uint16_t* srch = (tid < 128) ? gk_hi : gv_hi;
    const uint16_t* srcl = (tid < 128) ? gk_lo : gv_lo;
    uint32_t dsel = (tid < 128) ? 0u : 16384u;

#define ISSUE_KV(kt, buf) do {                                                   \
        uint32_t dst = sbase + SKV0 + (uint32_t)(buf) * 32768u + dsel;           \
        const uint16_t* sh = srch + ((size_t)bh * L_ + (size_t)(kt) * 64 + rr) * 64; \
        const uint16_t* sl = srcl + ((size_t)bh * L_ + (size_t)(kt) * 64 + rr) * 64; \
        _Pragma("unroll")                                                        \
        for (int i = 0; i < 4; i++) {                                            \
            uint32_t so = swz128((uint32_t)rr * 128u + (uint32_t)(g0 + i) * 16u);\
            cp16(dst + so,          sh + (g0 + i) * 8);                          \
            cp16(dst + 8192u + so,  sl + (g0 + i) * 8);                          \
        }                                                                        \
        cp_commit();                                                             \
    } while (0)

    // Prologue: Q tile copy + first K/V issue
    {
        const uint4* qh4 = (const uint4*)(gq_hi + ((size_t)bh * L_ + (size_t)qt * 128 + (tid >> 1)) * 64);
        const uint4* ql4 = (const uint4*)(gq_lo + ((size_t)bh * L_ + (size_t)qt * 128 + (tid >> 1)) * 64);
        int qg0 = (tid & 1) * 4;
#pragma unroll
        for (int i = 0; i < 4; i++) {
            uint32_t so = swz128((uint32_t)(tid >> 1) * 128u + (uint32_t)(qg0 + i) * 16u);
            *(uint4*)(smp + SQHI + so) = qh4[qg0 + i];
            *(uint4*)(smp + SQLO + so) = ql4[qg0 + i];
        }
    }
    ISSUE_KV(0, 0);
    __syncthreads();

    // Q A-fragments resident for the whole kernel
    uint32_t qh[4][4], ql[4][4];
    {
        int arow = 16 * w + (lane & 15);
#pragma unroll
        for (int ks = 0; ks < 4; ks++) {
            uint32_t off = swz128((uint32_t)arow * 128u
                                  + (uint32_t)(ks * 32 + ((lane & 16) ? 16 : 0)));
            ldsm4(qh[ks][0], qh[ks][1], qh[ks][2], qh[ks][3], sbase + SQHI + off);
            ldsm4(ql[ks][0], ql[ks][1], ql[ks][2], ql[ks][3], sbase + SQLO + off);
        }
    }

    float oc[8][4];
#pragma unroll
    for (int n = 0; n < 8; n++)
#pragma unroll
        for (int j = 0; j < 4; j++) oc[n][j] = 0.f;
    float lsum0 = 0.f, lsum1 = 0.f;

    const float Cc = 0.18033688011112042f;  // (1/8) * log2(e)
    int row0 = qt * 128 + 16 * w + (lane >> 2);
    int row1 = row0 + 8;

    for (int kt = 0; kt < nkt; ++kt) {
        if (kt + 1 < nkt) {
            ISSUE_KV(kt + 1, (kt + 1) & 1);
            cp_wait<1>();
        } else {
            cp_wait<0>();
        }
        __syncthreads();

        uint32_t kvb = sbase + SKV0 + (uint32_t)(kt & 1) * 32768u;

        // ---- S = Q K^T : 16x64 per warp ----
        float sc[8][4];
#pragma unroll
        for (int n = 0; n < 8; n++)
#pragma unroll
            for (int j = 0; j < 4; j++) sc[n][j] = 0.f;

#pragma unroll
        for (int ks = 0; ks < 4; ks++) {
#pragma unroll
            for (int np = 0; np < 4; np++) {
                int key = np * 16 + (lane & 7) + ((lane & 16) ? 8 : 0);
                uint32_t off = swz128((uint32_t)key * 128u
                                      + (uint32_t)(ks * 32 + ((lane & 8) ? 16 : 0)));
                uint32_t h0, h1, h2, h3, l0, l1, l2, l3;
                ldsm4(h0, h1, h2, h3, kvb + off);
                ldsm4(l0, l1, l2, l3, kvb + 8192u + off);
                mma_bf16(sc[2 * np],     qh[ks], h0, h1);
                mma_bf16(sc[2 * np],     qh[ks], l0, l1);
                mma_bf16(sc[2 * np],     ql[ks], h0, h1);
                mma_bf16(sc[2 * np + 1], qh[ks], h2, h3);
                mma_bf16(sc[2 * np + 1], qh[ks], l2, l3);
                mma_bf16(sc[2 * np + 1], ql[ks], h2, h3);
            }
        }

        // ---- softmax (unnormalized) ----
        bool edge = (kt == 0) || (kt >= 2 * qt);
        int colb = kt * 64 + 2 * (lane & 3);
#pragma unroll
        for (int n = 0; n < 8; n++) {
            float e0 = ex2f(sc[n][0] * Cc);
            float e1 = ex2f(sc[n][1] * Cc);
            float e2 = ex2f(sc[n][2] * Cc);
            float e3 = ex2f(sc[n][3] * Cc);
            if (edge) {
                int c0 = colb + 8 * n, c1 = c0 + 1;
                bool k00 = (c0 <= row0) && (c0 >= PREFIX || row0 < PREFIX);
                bool k01 = (c1 <= row0) && (c1 >= PREFIX || row0 < PREFIX);
                bool k10 = (c0 <= row1) && (c0 >= PREFIX || row1 < PREFIX);
                bool k11 = (c1 <= row1) && (c1 >= PREFIX || row1 < PREFIX);
                e0 = k00 ? e0 : 0.f;
                e1 = k01 ? e1 : 0.f;
                e2 = k10 ? e2 : 0.f;
                e3 = k11 ? e3 : 0.f;
            }
            sc[n][0] = e0; sc[n][1] = e1; sc[n][2] = e2; sc[n][3] = e3;
            lsum0 += e0 + e1;
            lsum1 += e2 + e3;
        }

        // ---- O += P V : P C-frags -> A-frags in registers ----
#pragma unroll
        for (int t = 0; t < 4; t++) {
            uint32_t ph[4], pl[4];
            {
                float* cA = sc[2 * t];
                float* cB = sc[2 * t + 1];
                uint32_t a0 = f2u(cA[0]), a1 = f2u(cA[1]);
                uint32_t a2 = f2u(cA[2]), a3 = f2u(cA[3]);
                uint32_t b0 = f2u(cB[0]), b1 = f2u(cB[1]);
                uint32_t b2 = f2u(cB[2]), b3 = f2u(cB[3]);
                ph[0] = prmt_hi16(a0, a1);
                ph[1] = prmt_hi16(a2, a3);
                ph[2] = prmt_hi16(b0, b1);
                ph[3] = prmt_hi16(b2, b3);
                pl[0] = cvt_bf16x2(cA[0] - __uint_as_float(a0 & 0xffff0000u),
                                   cA[1] - __uint_as_float(a1 & 0xffff0000u));
                pl[1] = cvt_bf16x2(cA[2] - __uint_as_float(a2 & 0xffff0000u),
                                   cA[3] - __uint_as_float(a3 & 0xffff0000u));
                pl[2] = cvt_bf16x2(cB[0] - __uint_as_float(b0 & 0xffff0000u),
                                   cB[1] - __uint_as_float(b1 & 0xffff0000u));
                pl[3] = cvt_bf16x2(cB[2] - __uint_as_float(b2 & 0xffff0000u),
                                   cB[3] - __uint_as_float(b3 & 0xffff0000u));
            }
            int key = t * 16 + (lane & 7) + ((lane & 8) ? 8 : 0);
#pragma unroll
            for (int dp = 0; dp < 4; dp++) {
                uint32_t off = swz128((uint32_t)key * 128u
                                      + (uint32_t)(dp * 32 + ((lane & 16) ? 16 : 0)));
                uint32_t h0, h1, h2, h3, l0, l1, l2, l3;
                ldsm4t(h0, h1, h2, h3, kvb + 16384u + off);
                ldsm4t(l0, l1, l2, l3, kvb + 24576u + off);
                mma_bf16(oc[2 * dp],     ph, h0, h1);
                mma_bf16(oc[2 * dp],     ph, l0, l1);
                mma_bf16(oc[2 * dp],     pl, h0, h1);
                mma_bf16(oc[2 * dp + 1], ph, h2, h3);
                mma_bf16(oc[2 * dp + 1], ph, l2, l3);
                mma_bf16(oc[2 * dp + 1], pl, h2, h3);
            }
        }
        __syncthreads();
    }
#undef ISSUE_KV

    // lane reduction of lsum
    lsum0 += __shfl_xor_sync(0xffffffffu, lsum0, 1);
    lsum0 += __shfl_xor_sync(0xffffffffu, lsum0, 2);
    lsum1 += __shfl_xor_sync(0xffffffffu, lsum1, 1);
    lsum1 += __shfl_xor_sync(0xffffffffu, lsum1, 2);
    float inv0 = 1.f / lsum0, inv1 = 1.f / lsum1;

    // store ctx as bf16 hi/lo
    int b = bh >> 3, h = bh & 7;
    size_t r0base = (size_t)(b * L_ + row0) * HIDDEN + h * 64;
    size_t r1base = (size_t)(b * L_ + row1) * HIDDEN + h * 64;
#pragma unroll
    for (int n = 0; n < 8; n++) {
        int d = 8 * n + 2 * (lane & 3);
        float v0 = oc[n][0] * inv0, v1 = oc[n][1] * inv0;
        float v2 = oc[n][2] * inv1, v3 = oc[n][3] * inv1;
        uint32_t u0 = f2u(v0), u1 = f2u(v1), u2 = f2u(v2), u3 = f2u(v3);
        *(uint32_t*)(gctx_hi + r0base + d) = prmt_hi16(u0, u1);
        *(uint32_t*)(gctx_lo + r0base + d) =
            cvt_bf16x2(v0 - __uint_as_float(u0 & 0xffff0000u),
                       v1 - __uint_as_float(u1 & 0xffff0000u));
        *(uint32_t*)(gctx_hi + r1base + d) = prmt_hi16(u2, u3);
        *(uint32_t*)(gctx_lo + r1base + d) =
            cvt_bf16x2(v2 - __uint_as_float(u2 & 0xffff0000u),
                       v3 - __uint_as_float(u3 & 0xffff0000u));
    }
}

// ============================================================
extern "C" void kernel_launch(void* const* d_in, const int* in_sizes, int n_in,
                              void* d_out, int out_size)
{
    const float* x     = (const float*)d_in[0];
    const float* w_in  = (const float*)d_in[1];
    const float* b_in  = (const float*)d_in[2];
    const float* w_out = (const float*)d_in[3];
    const float* b_out = (const float*)d_in[4];
    float* out = (float*)d_out;

    conv_x_kernel<<<(M_ROWS * HIDDEN / 4) / 256, 256>>>(x);
    conv_wT_kernel<<<dim3(3 * HIDDEN / 32, HIDDEN / 32), 256>>>(w_in, HIDDEN, 3 * HIDDEN, 0);
    conv_wT_kernel<<<dim3(HIDDEN / 32, HIDDEN / 32), 256>>>(w_out, HIDDEN, HIDDEN, 1);

    cudaFuncSetAttribute(gemm_bf16_kernel<0>,
                         cudaFuncAttributeMaxDynamicSharedMemorySize, 131072);
    gemm_bf16_kernel<0><<<dim3(12, 64), 256, 131072>>>(b_in, nullptr);

    cudaFuncSetAttribute(attn_mma_kernel,
                         cudaFuncAttributeMaxDynamicSharedMemorySize, ATTN_SMEM);
    attn_mma_kernel<<<dim3(16, 32), 256, ATTN_SMEM>>>();

    cudaFuncSetAttribute(gemm_bf16_kernel<1>,
                         cudaFuncAttributeMaxDynamicSharedMemorySize, 131072);
    gemm_bf16_kernel<1><<<dim3(4, 64), 256, 131072>>>(b_out, out);
}